// round 1
// baseline (speedup 1.0000x reference)
#include <cuda_runtime.h>

#define N      2048
#define NT     256
#define LOG2N  11
#define NCLS   10

// Row-invariant precomputed data (allocation-free scratch).
__device__ float2 g_tw[N / 2];   // exp(-2*pi*i*t/N), t in [0,1024)
__device__ float2 g_cw1[N];      // exp(i*w1[n])

__global__ void vpc_init(const float* __restrict__ w) {
    int i = blockIdx.x * blockDim.x + threadIdx.x;
    if (i < N / 2) {
        double th = -2.0 * 3.141592653589793238 * (double)i / (double)N;
        g_tw[i] = make_float2((float)cos(th), (float)sin(th));
    }
    if (i < N) {
        float s, c;
        sincosf(w[N + i], &s, &c);
        g_cw1[i] = make_float2(c, s);
    }
}

__device__ __forceinline__ float2 cmul(float2 a, float2 b) {
    return make_float2(a.x * b.x - a.y * b.y, a.x * b.y + a.y * b.x);
}

__global__ __launch_bounds__(NT) void vpc_main(const float* __restrict__ x,
                                               const float* __restrict__ w,
                                               float* __restrict__ out) {
    __shared__ float2 sA[N];
    __shared__ float2 sB[N];
    __shared__ float2 tw[N / 2];

    const int tid = threadIdx.x;
    const int row = blockIdx.x;
    const float2* xr = (const float2*)(x + (size_t)row * N);   // pairs
    const float2* w0 = (const float2*)w;                        // pairs of w[0..N)

    // Twiddle table -> shared
#pragma unroll
    for (int j = 0; j < (N / 2) / NT; j++)
        tw[tid + j * NT] = g_tw[tid + j * NT];

    // Layer 0: z = exp(i*(x + w0)); adjacent-pair butterfly (norm dropped).
#pragma unroll
    for (int j = 0; j < 4; j++) {
        int pp = tid + j * NT;           // pair index < 1024
        float2 xv = xr[pp];
        float2 wv = w0[pp];
        float s0, c0, s1, c1;
        sincosf(xv.x + wv.x, &s0, &c0);
        sincosf(xv.y + wv.y, &s1, &c1);
        sA[2 * pp]     = make_float2(c0 + c1, s0 + s1);
        sA[2 * pp + 1] = make_float2(c0 - c1, s0 - s1);
    }
    __syncthreads();

    // 2048-pt FFT: radix-2 Stockham DIF (auto-sort), 11 stages, ping-pong sA<->sB.
    float2* src = sA;
    float2* dst = sB;
#pragma unroll
    for (int stage = 0; stage < LOG2N; stage++) {
        const int slog = stage;
        const int s = 1 << slog;
        const int m = (N / 2) >> slog;
#pragma unroll
        for (int t = tid; t < N / 2; t += NT) {
            int p = t >> slog;
            int q = t & (s - 1);
            float2 a = src[q + (p << slog)];
            float2 b = src[q + ((p + m) << slog)];
            float2 wp = tw[p << slog];                 // exp(-2pi*i*p/n), n = N/s
            float2 sum = make_float2(a.x + b.x, a.y + b.y);
            float2 dif = make_float2(a.x - b.x, a.y - b.y);
            int o = q + (p << (slog + 1));
            dst[o]     = sum;
            dst[o + s] = cmul(dif, wp);
        }
        __syncthreads();
        float2* tmp = src; src = dst; dst = tmp;
    }
    // Result of layer-0 FFT now in src (== sB).

    // Layer 1: z *= exp(i*w1); adjacent-pair butterfly -> dst.
#pragma unroll
    for (int j = 0; j < 4; j++) {
        int pp = tid + j * NT;
        float2 a = cmul(src[2 * pp],     g_cw1[2 * pp]);
        float2 b = cmul(src[2 * pp + 1], g_cw1[2 * pp + 1]);
        dst[2 * pp]     = make_float2(a.x + b.x, a.y + b.y);
        dst[2 * pp + 1] = make_float2(a.x - b.x, a.y - b.y);
    }
    __syncthreads();

    // Final FFT: only bins 0..9 needed -> direct DFT, register accumulators.
    float2 acc[NCLS];
#pragma unroll
    for (int k = 0; k < NCLS; k++) acc[k] = make_float2(0.f, 0.f);

#pragma unroll
    for (int j = 0; j < N / NT; j++) {
        int n = tid + j * NT;
        float2 v = dst[n];
#pragma unroll
        for (int k = 0; k < NCLS; k++) {
            int idx = (k * n) & (N - 1);
            float2 wv = tw[idx & (N / 2 - 1)];
            float sgn = (idx & (N / 2)) ? -1.0f : 1.0f;   // exp shifted by pi
            float wx = wv.x * sgn, wy = wv.y * sgn;
            acc[k].x += v.x * wx - v.y * wy;
            acc[k].y += v.x * wy + v.y * wx;
        }
    }

    // Warp reduce 10 complex accumulators.
#pragma unroll
    for (int k = 0; k < NCLS; k++) {
#pragma unroll
        for (int off = 16; off > 0; off >>= 1) {
            acc[k].x += __shfl_down_sync(0xFFFFFFFFu, acc[k].x, off);
            acc[k].y += __shfl_down_sync(0xFFFFFFFFu, acc[k].y, off);
        }
    }

    // Cross-warp reduce via shared (reuse src buffer; DFT reads were from dst/tw).
    float2* red   = src;                          // 8 warps * 10 bins
    float* logits = (float*)(src + 8 * NCLS);     // 10 floats after red
    int lane = tid & 31, wrp = tid >> 5;
    if (lane == 0) {
#pragma unroll
        for (int k = 0; k < NCLS; k++) red[wrp * NCLS + k] = acc[k];
    }
    __syncthreads();

    if (tid < NCLS) {
        float re = 0.f, im = 0.f;
#pragma unroll
        for (int wq = 0; wq < NT / 32; wq++) {
            re += red[wq * NCLS + tid].x;
            im += red[wq * NCLS + tid].y;
        }
        float r2 = re * re + im * im;
        // sin(atan2(im,re)) = im / |z|; scalings are positive -> phases unchanged.
        float l = (r2 > 0.f) ? 5.0f * im * rsqrtf(r2) : 0.0f;
        logits[tid] = l;
    }
    __syncthreads();

    if (tid < NCLS) {
        float m = -1e30f;
#pragma unroll
        for (int k = 0; k < NCLS; k++) m = fmaxf(m, logits[k]);
        float sum = 0.f;
#pragma unroll
        for (int k = 0; k < NCLS; k++) sum += expf(logits[k] - m);
        out[(size_t)row * NCLS + tid] = expf(logits[tid] - m) / sum;
    }
}

extern "C" void kernel_launch(void* const* d_in, const int* in_sizes, int n_in,
                              void* d_out, int out_size) {
    const float* x = (const float*)d_in[0];     // (8192, 2048) fp32
    const float* w = (const float*)d_in[1];     // (4096,) fp32
    float* out = (float*)d_out;                 // (8192, 10) fp32

    vpc_init<<<(N + 255) / 256, 256>>>(w);
    vpc_main<<<8192, NT>>>(x, w, out);
}

// round 2
// speedup vs baseline: 1.8875x; 1.8875x over previous
#include <cuda_runtime.h>
#include <math_constants.h>

#define N     2048
#define NT    256
#define NCLS  10
#define C707  0.70710678118654752440f

// pad mapping: one extra float2 per 8 to break 8/64-stride bank conflicts
#define F(i) ((i) + ((i) >> 3))
#define SPAD 2304   // F(2047)=2302 -> 2304

__device__ float2 g_cw1[N];   // exp(i*w1[n]), row-invariant

__global__ void vpc_init(const float* __restrict__ w) {
    int i = blockIdx.x * blockDim.x + threadIdx.x;
    if (i < N) {
        float s, c;
        sincosf(w[N + i], &s, &c);
        g_cw1[i] = make_float2(c, s);
    }
}

__device__ __forceinline__ float2 cmul(float2 a, float2 b) {
    return make_float2(a.x * b.x - a.y * b.y, a.x * b.y + a.y * b.x);
}
__device__ __forceinline__ float2 cadd(float2 a, float2 b) { return make_float2(a.x + b.x, a.y + b.y); }
__device__ __forceinline__ float2 csub(float2 a, float2 b) { return make_float2(a.x - b.x, a.y - b.y); }
__device__ __forceinline__ float2 mul_mi(float2 z) { return make_float2(z.y, -z.x); }   // z * (-i)
__device__ __forceinline__ float2 mul_pi(float2 z) { return make_float2(-z.y, z.x); }   // z * (+i)

// DFT8 (forward, W8 = e^{-i pi/4}) of x0..x7 -> X0..X7
#define DFT8(x0,x1,x2,x3,x4,x5,x6,x7, X0,X1,X2,X3,X4,X5,X6,X7) do {            \
    float2 t0 = cadd(x0, x4), t1 = csub(x0, x4);                               \
    float2 t2 = cadd(x2, x6), t3 = csub(x2, x6);                               \
    float2 E0 = cadd(t0, t2), E2 = csub(t0, t2);                               \
    float2 E1 = cadd(t1, mul_mi(t3)), E3 = cadd(t1, mul_pi(t3));               \
    float2 s0 = cadd(x1, x5), s1 = csub(x1, x5);                               \
    float2 s2 = cadd(x3, x7), s3 = csub(x3, x7);                               \
    float2 O0 = cadd(s0, s2), O2 = csub(s0, s2);                               \
    float2 O1 = cadd(s1, mul_mi(s3)), O3 = cadd(s1, mul_pi(s3));               \
    float2 W1O = make_float2(C707 * (O1.x + O1.y), C707 * (O1.y - O1.x));      \
    float2 W2O = mul_mi(O2);                                                   \
    float2 W3O = make_float2(C707 * (O3.y - O3.x), -C707 * (O3.x + O3.y));     \
    X0 = cadd(E0, O0);  X4 = csub(E0, O0);                                     \
    X1 = cadd(E1, W1O); X5 = csub(E1, W1O);                                    \
    X2 = cadd(E2, W2O); X6 = csub(E2, W2O);                                    \
    X3 = cadd(E3, W3O); X7 = csub(E3, W3O);                                    \
} while (0)

template <int SL>
__device__ __forceinline__ void radix8_stage(const float2* __restrict__ src,
                                             float2* __restrict__ dst, int t) {
    const int s = 1 << SL;
    float2 a0 = src[F(t + 0 * 256)], a1 = src[F(t + 1 * 256)];
    float2 a2 = src[F(t + 2 * 256)], a3 = src[F(t + 3 * 256)];
    float2 a4 = src[F(t + 4 * 256)], a5 = src[F(t + 5 * 256)];
    float2 a6 = src[F(t + 6 * 256)], a7 = src[F(t + 7 * 256)];
    float2 X0, X1, X2, X3, X4, X5, X6, X7;
    DFT8(a0, a1, a2, a3, a4, a5, a6, a7, X0, X1, X2, X3, X4, X5, X6, X7);
    // twiddles exp(-2*pi*i * p*k / n), p*s = t & ~(s-1), theta1 = -pi*(p*s)/1024
    float th = (-(float)CUDART_PI / 1024.0f) * (float)(t & ~(s - 1));
    float2 w1, w2, w3, w4;
    __sincosf(th,        &w1.y, &w1.x);
    __sincosf(2.0f * th, &w2.y, &w2.x);
    __sincosf(3.0f * th, &w3.y, &w3.x);
    __sincosf(4.0f * th, &w4.y, &w4.x);
    float2 w5 = cmul(w1, w4), w6 = cmul(w2, w4), w7 = cmul(w3, w4);
    int ob = (t & (s - 1)) + ((t >> SL) << (SL + 3));   // q + 8*s*p
    dst[F(ob + 0 * s)] = X0;
    dst[F(ob + 1 * s)] = cmul(X1, w1);
    dst[F(ob + 2 * s)] = cmul(X2, w2);
    dst[F(ob + 3 * s)] = cmul(X3, w3);
    dst[F(ob + 4 * s)] = cmul(X4, w4);
    dst[F(ob + 5 * s)] = cmul(X5, w5);
    dst[F(ob + 6 * s)] = cmul(X6, w6);
    dst[F(ob + 7 * s)] = cmul(X7, w7);
}

__global__ __launch_bounds__(NT) void vpc_main(const float* __restrict__ x,
                                               const float* __restrict__ w,
                                               float* __restrict__ out) {
    __shared__ float2 sA[SPAD];
    __shared__ float2 sB[SPAD];

    const int tid = threadIdx.x;
    const int row = blockIdx.x;
    const float4* xr = (const float4*)(x + (size_t)row * N);   // 2 pairs per load
    const float4* w0 = (const float4*)w;

    // ---- Layer 0: z = exp(i*(x+w0)); adjacent-pair butterfly (norms dropped) ----
#pragma unroll
    for (int j = 0; j < 2; j++) {
        int qq = tid + j * NT;            // quad index < 512 (covers 2 pairs)
        float4 xv = xr[qq];
        float4 wv = w0[qq];
        float s0, c0, s1, c1, s2, c2, s3, c3;
        __sincosf(xv.x + wv.x, &s0, &c0);
        __sincosf(xv.y + wv.y, &s1, &c1);
        __sincosf(xv.z + wv.z, &s2, &c2);
        __sincosf(xv.w + wv.w, &s3, &c3);
        int b = 4 * qq;
        sA[F(b + 0)] = make_float2(c0 + c1, s0 + s1);
        sA[F(b + 1)] = make_float2(c0 - c1, s0 - s1);
        sA[F(b + 2)] = make_float2(c2 + c3, s2 + s3);
        sA[F(b + 3)] = make_float2(c2 - c3, s2 - s3);
    }
    __syncthreads();

    // ---- FFT 2048 = 8 * 8 * 8 * 4, Stockham autosort ----
    radix8_stage<0>(sA, sB, tid); __syncthreads();
    radix8_stage<3>(sB, sA, tid); __syncthreads();
    radix8_stage<6>(sA, sB, tid); __syncthreads();
    // radix-4 final stage: s=512, no twiddle, result -> sA (natural order)
#pragma unroll
    for (int jj = 0; jj < 2; jj++) {
        int q = tid + jj * NT;
        float2 a = sB[F(q + 0 * 512)], b = sB[F(q + 1 * 512)];
        float2 c = sB[F(q + 2 * 512)], d = sB[F(q + 3 * 512)];
        float2 apc = cadd(a, c), amc = csub(a, c);
        float2 bpd = cadd(b, d), bmd = csub(b, d);
        sA[F(q + 0 * 512)] = cadd(apc, bpd);
        sA[F(q + 1 * 512)] = cadd(amc, mul_mi(bmd));
        sA[F(q + 2 * 512)] = csub(apc, bpd);
        sA[F(q + 3 * 512)] = cadd(amc, mul_pi(bmd));
    }
    __syncthreads();

    // ---- Layer 1: z *= exp(i*w1); pair butterfly -> y in sB ----
#pragma unroll
    for (int j = 0; j < 4; j++) {
        int pp = tid + j * NT;
        float2 a = cmul(sA[F(2 * pp)],     g_cw1[2 * pp]);
        float2 b = cmul(sA[F(2 * pp + 1)], g_cw1[2 * pp + 1]);
        sB[F(2 * pp)]     = cadd(a, b);
        sB[F(2 * pp + 1)] = csub(a, b);
    }
    __syncthreads();

    // ---- Final: bins 0..9 of FFT(y). n = 256a + b, thread owns b = tid.
    // S_b(j) = DFT8 over a of y[256a+b]; X_k = sum_b W2048^{b k} S_b(k mod 8).
    float2 v0 = sB[F(tid + 0 * 256)], v1 = sB[F(tid + 1 * 256)];
    float2 v2 = sB[F(tid + 2 * 256)], v3 = sB[F(tid + 3 * 256)];
    float2 v4 = sB[F(tid + 4 * 256)], v5 = sB[F(tid + 5 * 256)];
    float2 v6 = sB[F(tid + 6 * 256)], v7 = sB[F(tid + 7 * 256)];
    float2 S0, S1, S2, S3, S4, S5, S6, S7;
    DFT8(v0, v1, v2, v3, v4, v5, v6, v7, S0, S1, S2, S3, S4, S5, S6, S7);

    float2 acc[NCLS];
    {
        float2 w1t;
        __sincosf((-(float)CUDART_PI / 1024.0f) * (float)tid, &w1t.y, &w1t.x);
        float2 wk = make_float2(1.0f, 0.0f);
        acc[0] = S0;
        wk = cmul(wk, w1t); acc[1] = cmul(wk, S1);
        wk = cmul(wk, w1t); acc[2] = cmul(wk, S2);
        wk = cmul(wk, w1t); acc[3] = cmul(wk, S3);
        wk = cmul(wk, w1t); acc[4] = cmul(wk, S4);
        wk = cmul(wk, w1t); acc[5] = cmul(wk, S5);
        wk = cmul(wk, w1t); acc[6] = cmul(wk, S6);
        wk = cmul(wk, w1t); acc[7] = cmul(wk, S7);
        wk = cmul(wk, w1t); acc[8] = cmul(wk, S0);
        wk = cmul(wk, w1t); acc[9] = cmul(wk, S1);
    }

    // Warp reduction
#pragma unroll
    for (int k = 0; k < NCLS; k++) {
#pragma unroll
        for (int off = 16; off > 0; off >>= 1) {
            acc[k].x += __shfl_down_sync(0xFFFFFFFFu, acc[k].x, off);
            acc[k].y += __shfl_down_sync(0xFFFFFFFFu, acc[k].y, off);
        }
    }

    // Cross-warp reduction via sA (free now)
    float2* red   = sA;
    float* logits = (float*)(sA + 8 * NCLS);
    int lane = tid & 31, wrp = tid >> 5;
    if (lane == 0) {
#pragma unroll
        for (int k = 0; k < NCLS; k++) red[wrp * NCLS + k] = acc[k];
    }
    __syncthreads();

    if (tid < NCLS) {
        float re = 0.f, im = 0.f;
#pragma unroll
        for (int wq = 0; wq < NT / 32; wq++) {
            re += red[wq * NCLS + tid].x;
            im += red[wq * NCLS + tid].y;
        }
        float r2 = re * re + im * im;
        // sin(atan2(im,re)) = im/|z|; dropped norms are positive -> phases unchanged
        logits[tid] = (r2 > 0.f) ? 5.0f * im * rsqrtf(r2) : 0.0f;
    }
    __syncthreads();

    if (tid < NCLS) {
        float m = -1e30f;
#pragma unroll
        for (int k = 0; k < NCLS; k++) m = fmaxf(m, logits[k]);
        float sum = 0.f;
#pragma unroll
        for (int k = 0; k < NCLS; k++) sum += expf(logits[k] - m);
        out[(size_t)row * NCLS + tid] = expf(logits[tid] - m) / sum;
    }
}

extern "C" void kernel_launch(void* const* d_in, const int* in_sizes, int n_in,
                              void* d_out, int out_size) {
    const float* x = (const float*)d_in[0];     // (8192, 2048) fp32
    const float* w = (const float*)d_in[1];     // (4096,) fp32
    float* out = (float*)d_out;                 // (8192, 10) fp32

    vpc_init<<<(N + 255) / 256, 256>>>(w);
    vpc_main<<<8192, NT>>>(x, w, out);
}